// round 4
// baseline (speedup 1.0000x reference)
#include <cuda_runtime.h>

// SMFNet B=2,N=8192,D=64,DV=64,M=3 — chord mask = diag + superdiag(wrap).
// Per iter: V'[i] = a_i V[i] + c_i V[i+1].  Unrolled over M=3:
//   V3[i] = (w0 X[i] + w1 X[i+1] + w2 X[i+2] + w3 X[i+3]) @ Wg + (sum w) * bg
// K1: A[m,i] = X[i]·Wf[m][:,i] + bf[m][i] ; C[m,i] = X[i]·Wf[m][:,i+1] + bf[m][i+1]
// K2: 4-tap weights from A/C, combine X rows, matvec @Wg (packed f32x2 FMA).

#define Bc   2
#define Nc   8192
#define Dc   64

// ---------------- scratch ----------------
__device__ float g_A[Bc][3][Nc];
__device__ float g_C[Bc][3][Nc];

// ---------------- packed f32x2 helpers ----------------
__device__ __forceinline__ unsigned long long pack2(float x, float y) {
    unsigned long long r;
    asm("mov.b64 %0, {%1, %2};" : "=l"(r) : "f"(x), "f"(y));
    return r;
}
__device__ __forceinline__ void unpack2(unsigned long long v, float& x, float& y) {
    asm("mov.b64 {%0, %1}, %2;" : "=f"(x), "=f"(y) : "l"(v));
}
__device__ __forceinline__ void fma2(unsigned long long& d,
                                     unsigned long long a, unsigned long long b) {
    asm("fma.rn.f32x2 %0, %1, %2, %3;" : "=l"(d) : "l"(a), "l"(b), "l"(d));
}

// ================= K1: A/C scalars, coalesced Wf =================
// grid (N/256, 3, 2), block 256. Thread t owns row gi=i0+t:
//   A[gi] uses Wf column gi, C[gi] uses column gi+1 (wrap).
#define K1ROWS 256
#define K1PAD  65               // scalar staging only; 65 mod 32 == 1
#define K1_SMEM_BYTES (K1ROWS * K1PAD * 4)

__global__ __launch_bounds__(256, 2)
void smf_ac_kernel(const float* __restrict__ X,
                   const float* __restrict__ Wf,
                   const float* __restrict__ bf)
{
    extern __shared__ float Xs[];   // [K1ROWS][K1PAD]
    const int t  = threadIdx.x;
    const int i0 = blockIdx.x * K1ROWS;
    const int m  = blockIdx.y;
    const int b  = blockIdx.z;

    // stage X rows [i0, i0+256): scalar, coalesced (consecutive t -> consecutive d)
    {
        const float* Xb = X + (size_t)b * Nc * Dc + (size_t)i0 * Dc;
        #pragma unroll
        for (int idx = t; idx < K1ROWS * 64; idx += 256) {
            int j = idx >> 6, d = idx & 63;
            Xs[j * K1PAD + d] = Xb[idx];
        }
    }
    __syncthreads();

    const int gi  = i0 + t;
    const int gi1 = (gi + 1) & (Nc - 1);
    const float* Wm = Wf + (size_t)m * Dc * Nc;

    float a = 0.f, c = 0.f;
    #pragma unroll 16
    for (int d = 0; d < Dc; d++) {
        float xv = Xs[t * K1PAD + d];
        const float* p = Wm + (size_t)d * Nc;
        a = fmaf(xv, __ldg(p + gi),  a);
        c = fmaf(xv, __ldg(p + gi1), c);
    }
    g_A[b][m][gi] = a + bf[m * Nc + gi];
    g_C[b][m][gi] = c + bf[m * Nc + gi1];
}

// ================= K2: weights + combine + matvec =================
#define TROWS 32
#define XROWS 35
#define XPAD  68                // float4-staged buffer: stride*4 divisible by 16
#define XWPAD 65                // scalar-only buffer: conflict-free columns
#define ACR   36
#define NTHREADS 256

#define OFF_XS    0
#define OFF_WGS   (OFF_XS  + XROWS*XPAD)     // 2380 floats -> byte 9520 (16B-aligned)
#define OFF_XWS   (OFF_WGS + 64*64)
#define OFF_AS    (OFF_XWS + TROWS*XWPAD)
#define OFF_CS    (OFF_AS  + 3*ACR)
#define OFF_WC    (OFF_CS  + 3*ACR)
#define OFF_WSUM  (OFF_WC  + TROWS*4)
#define OFF_BGS   (OFF_WSUM + TROWS)
#define SMEM_FLOATS (OFF_BGS + 64)
#define K2_SMEM_BYTES (SMEM_FLOATS * 4)

__global__ __launch_bounds__(NTHREADS, 4)
void smf_mix_kernel(const float* __restrict__ X,
                    const float* __restrict__ Wg,
                    const float* __restrict__ bg,
                    float* __restrict__ out)
{
    extern __shared__ float sm[];
    float* Xs   = sm + OFF_XS;
    float* Wgs  = sm + OFF_WGS;
    float* Xws  = sm + OFF_XWS;
    float* As   = sm + OFF_AS;
    float* Cs   = sm + OFF_CS;
    float* Wc   = sm + OFF_WC;
    float* Wsum = sm + OFF_WSUM;
    float* bgs  = sm + OFF_BGS;

    const int t  = threadIdx.x;
    const int b  = blockIdx.y;
    const int r0 = blockIdx.x * TROWS;
    const float* Xb = X + (size_t)b * Nc * Dc;

    // ---- stage Wg, bg, X rows [r0, r0+35) (wrap), and A/C scalars ----
    {
        const float4* Wg4 = reinterpret_cast<const float4*>(Wg);
        #pragma unroll
        for (int idx = t; idx < 64 * 16; idx += NTHREADS)
            *reinterpret_cast<float4*>(&Wgs[idx * 4]) = Wg4[idx];
        if (t < 64) bgs[t] = bg[t];
        const float4* Xb4 = reinterpret_cast<const float4*>(Xb);
        #pragma unroll
        for (int idx = t; idx < XROWS * 16; idx += NTHREADS) {
            int j = idx >> 4, q = idx & 15;
            int gi = (r0 + j) & (Nc - 1);
            *reinterpret_cast<float4*>(&Xs[j * XPAD + q * 4]) = Xb4[gi * 16 + q];
        }
        if (t < 204) {
            int s = t;                  // [0,102): A ; [102,204): C
            int isC = s >= 102; if (isC) s -= 102;
            int m = s / 34, j = s - 34 * m;
            int gi = (r0 + j) & (Nc - 1);
            float v = isC ? g_C[b][m][gi] : g_A[b][m][gi];
            (isC ? Cs : As)[m * ACR + j] = v;
        }
    }
    __syncthreads();

    // ---- 4-tap weights per output row ----
    if (t < TROWS) {
        const int j = t;
        float A1i  = As[0 * ACR + j], A1i1 = As[0 * ACR + j + 1], A1i2 = As[0 * ACR + j + 2];
        float C1i  = Cs[0 * ACR + j], C1i1 = Cs[0 * ACR + j + 1], C1i2 = Cs[0 * ACR + j + 2];
        float A2i  = As[1 * ACR + j], A2i1 = As[1 * ACR + j + 1];
        float C2i  = Cs[1 * ACR + j], C2i1 = Cs[1 * ACR + j + 1];
        float A3   = As[2 * ACR + j], C3   = Cs[2 * ACR + j];
        float w0 = A3 * A2i * A1i;
        float w1 = A3 * (A2i * C1i + C2i * A1i1) + C3 * A2i1 * A1i1;
        float w2 = A3 * C2i * C1i1 + C3 * (A2i1 * C1i1 + C2i1 * A1i2);
        float w3 = C3 * C2i1 * C1i2;
        Wc[j * 4 + 0] = w0; Wc[j * 4 + 1] = w1;
        Wc[j * 4 + 2] = w2; Wc[j * 4 + 3] = w3;
        Wsum[j] = w0 + w1 + w2 + w3;
    }
    __syncthreads();

    // ---- combined rows Xw[j] = sum_k w_k X[j+k] ----
    #pragma unroll
    for (int idx = t; idx < TROWS * 64; idx += NTHREADS) {
        int j = idx >> 6, d = idx & 63;
        float v = Wc[j * 4 + 0] * Xs[ j      * XPAD + d]
                + Wc[j * 4 + 1] * Xs[(j + 1) * XPAD + d]
                + Wc[j * 4 + 2] * Xs[(j + 2) * XPAD + d]
                + Wc[j * 4 + 3] * Xs[(j + 3) * XPAD + d];
        Xws[j * XWPAD + d] = v;
    }
    __syncthreads();

    // ---- matvec Xw @ Wg + wsum*bg, packed f32x2 FMA ----
    // thread tile: rows {rc, rc+16}, cols [e0, e0+4)
    {
        const int rc = t & 15;
        const int e0 = (t >> 4) * 4;
        unsigned long long acc00 = 0, acc01 = 0, acc10 = 0, acc11 = 0;

        #pragma unroll 8
        for (int d = 0; d < Dc; d++) {
            const unsigned long long* wp =
                reinterpret_cast<const unsigned long long*>(&Wgs[d * 64 + e0]);
            unsigned long long w01 = wp[0];
            unsigned long long w23 = wp[1];
            float x0 = Xws[ rc       * XWPAD + d];
            float x1 = Xws[(rc + 16) * XWPAD + d];
            unsigned long long xx0 = pack2(x0, x0);
            unsigned long long xx1 = pack2(x1, x1);
            fma2(acc00, xx0, w01);
            fma2(acc01, xx0, w23);
            fma2(acc10, xx1, w01);
            fma2(acc11, xx1, w23);
        }

        float a0, a1, a2, a3;
        // row rc
        {
            const int j  = rc;
            const int gi = (r0 + j) & (Nc - 1);
            const float ws = Wsum[j];
            unpack2(acc00, a0, a1); unpack2(acc01, a2, a3);
            float4 o;
            o.x = a0 + ws * bgs[e0 + 0];
            o.y = a1 + ws * bgs[e0 + 1];
            o.z = a2 + ws * bgs[e0 + 2];
            o.w = a3 + ws * bgs[e0 + 3];
            *reinterpret_cast<float4*>(&out[((size_t)b * Nc + gi) * 64 + e0]) = o;
        }
        // row rc+16
        {
            const int j  = rc + 16;
            const int gi = (r0 + j) & (Nc - 1);
            const float ws = Wsum[j];
            unpack2(acc10, a0, a1); unpack2(acc11, a2, a3);
            float4 o;
            o.x = a0 + ws * bgs[e0 + 0];
            o.y = a1 + ws * bgs[e0 + 1];
            o.z = a2 + ws * bgs[e0 + 2];
            o.w = a3 + ws * bgs[e0 + 3];
            *reinterpret_cast<float4*>(&out[((size_t)b * Nc + gi) * 64 + e0]) = o;
        }
    }
}

extern "C" void kernel_launch(void* const* d_in, const int* in_sizes, int n_in,
                              void* d_out, int out_size)
{
    const float* X  = (const float*)d_in[0];   // (2, 8192, 64)
    const float* Wg = (const float*)d_in[1];   // (64, 64)
    const float* bg = (const float*)d_in[2];   // (64,)
    const float* Wf = (const float*)d_in[3];   // (3, 64, 8192)
    const float* bf = (const float*)d_in[4];   // (3, 8192)
    float* out = (float*)d_out;                // (2, 8192, 64)

    cudaFuncSetAttribute(smf_ac_kernel,
                         cudaFuncAttributeMaxDynamicSharedMemorySize, K1_SMEM_BYTES);
    cudaFuncSetAttribute(smf_mix_kernel,
                         cudaFuncAttributeMaxDynamicSharedMemorySize, K2_SMEM_BYTES);

    dim3 g1(Nc / K1ROWS, 3, Bc);               // (32, 3, 2)
    smf_ac_kernel<<<g1, 256, K1_SMEM_BYTES>>>(X, Wf, bf);

    dim3 g2(Nc / TROWS, Bc);                   // (256, 2)
    smf_mix_kernel<<<g2, NTHREADS, K2_SMEM_BYTES>>>(X, Wg, bg, out);
}